// round 10
// baseline (speedup 1.0000x reference)
#include <cuda_runtime.h>
#include <math.h>

#define N3 (128*128*128)
#define NZH 65                       // Hermitian half length along z
#define KLINES (128*65)              // 8320 k-space lines for y/x passes

__device__ float2 d_kmesh[128*128*NZH];  // half-spectrum mesh (8.5 MB)
__device__ float  d_rho[N3];             // dense real mesh (8 MB)

// ---------------------------------------------------------------------------
__device__ __forceinline__ float2 cadd(float2 a, float2 b){ return make_float2(a.x+b.x, a.y+b.y); }
__device__ __forceinline__ float2 csub(float2 a, float2 b){ return make_float2(a.x-b.x, a.y-b.y); }
__device__ __forceinline__ float2 cmul(float2 a, float2 w){ return make_float2(a.x*w.x-a.y*w.y, a.x*w.y+a.y*w.x); }

__device__ __forceinline__ void inv3x3(const float* __restrict__ cell,
                                       float inv[9], float& det) {
    float a = __ldg(cell+0), b = __ldg(cell+1), c = __ldg(cell+2);
    float d = __ldg(cell+3), e = __ldg(cell+4), f = __ldg(cell+5);
    float g = __ldg(cell+6), h = __ldg(cell+7), i = __ldg(cell+8);
    float C00 =  (e*i - f*h), C01 = -(d*i - f*g), C02 =  (d*h - e*g);
    float C10 = -(b*i - c*h), C11 =  (a*i - c*g), C12 = -(a*h - b*g);
    float C20 =  (b*f - c*e), C21 = -(a*f - c*d), C22 =  (a*e - b*d);
    det = a*C00 + b*C01 + c*C02;
    float idet = 1.0f / det;
    inv[0]=C00*idet; inv[1]=C10*idet; inv[2]=C20*idet;
    inv[3]=C01*idet; inv[4]=C11*idet; inv[5]=C21*idet;
    inv[6]=C02*idet; inv[7]=C12*idet; inv[8]=C22*idet;
}

__global__ void k_zero() {
    int i = blockIdx.x * blockDim.x + threadIdx.x;   // 524288 float4s (8 MB)
    ((float4*)d_rho)[i] = make_float4(0.f, 0.f, 0.f, 0.f);
}

// ---------------------------------------------------------------------------
// Radix-4 Stockham stage — per-warp line ownership; lane = butterfly index.
// ---------------------------------------------------------------------------
template<int CONJ, int S>
__device__ __forceinline__ void r4_stage(const float2* __restrict__ cur,
                                         float2* __restrict__ nxt,
                                         const float2* __restrict__ tw,
                                         int off, int t) {
    int q  = t & (S - 1);
    int sp = t - q;
    float2 a0 = cur[off + t];
    float2 a1 = cur[off + t + 32];
    float2 a2 = cur[off + t + 64];
    float2 a3 = cur[off + t + 96];
    float2 t02 = cadd(a0, a2), d02 = csub(a0, a2);
    float2 t13 = cadd(a1, a3), d13 = csub(a1, a3);
    float2 y0 = cadd(t02, t13);
    float2 y2 = csub(t02, t13);
    float2 jd;
    if (CONJ) jd = make_float2(-d13.y,  d13.x);
    else      jd = make_float2( d13.y, -d13.x);
    float2 y1 = cadd(d02, jd);
    float2 y3 = csub(d02, jd);
    float2 w1 = tw[sp], w2 = tw[2*sp], w3 = tw[3*sp];
    if (CONJ) { w1.y = -w1.y; w2.y = -w2.y; w3.y = -w3.y; }
    int o = off + t + 3*sp;
    nxt[o]       = y0;
    nxt[o + S]   = cmul(y1, w1);
    nxt[o + 2*S] = cmul(y2, w2);
    nxt[o + 3*S] = cmul(y3, w3);
}

// ILP-2: each warp runs TWO independent lines through the three stages.
template<int CONJ>
__device__ __forceinline__ void fft_r4_stages_x2(float2* A, float2* B,
                                                 const float2* tw,
                                                 int off0, int off1, int lane) {
    r4_stage<CONJ, 1 >(A, B, tw, off0, lane);
    r4_stage<CONJ, 1 >(A, B, tw, off1, lane); __syncwarp();
    r4_stage<CONJ, 4 >(B, A, tw, off0, lane);
    r4_stage<CONJ, 4 >(B, A, tw, off1, lane); __syncwarp();
    r4_stage<CONJ, 16>(A, B, tw, off0, lane);
    r4_stage<CONJ, 16>(A, B, tw, off1, lane); __syncwarp();
}

// per-warp twiddle-free final radix-2 (src -> dst, natural order)
__device__ __forceinline__ void r2_final_warp(const float2* __restrict__ src,
                                              float2* __restrict__ dst,
                                              int off, int lane) {
    #pragma unroll
    for (int t = lane; t < 64; t += 32) {
        float2 a = src[off + t], b = src[off + t + 64];
        dst[off + t]      = cadd(a, b);
        dst[off + t + 64] = csub(a, b);
    }
}

__device__ __forceinline__ void init_tw(float2* tw, int tid) {
    if (tid < 128) {
        float s, c;
        sincospif((float)tid * (1.0f / 64.0f), &s, &c);
        tw[tid] = make_float2(c, -s);
    }
}

// ---------------------------------------------------------------------------
// z forward r2c (two-for-one): warp w handles packed lines gw0=blk*16+w and
// gw0+8 (each packs 2 real lines). 512 blocks x 8 warps.
// ---------------------------------------------------------------------------
__global__ void k_fft_z_fwd() {
    __shared__ float2 bufA[16 * 129];
    __shared__ float2 bufB[16 * 129];
    __shared__ float2 tw[128];
    int tid = threadIdx.x, lane = tid & 31, w = tid >> 5;
    int off0 = w * 129, off1 = (w + 8) * 129;
    int gw0 = blockIdx.x * 16 + w, gw1 = gw0 + 8;
    init_tw(tw, tid);
    const float* rpA0 = d_rho + (2*gw0) * 128;
    const float* rpB0 = rpA0 + 128;
    const float* rpA1 = d_rho + (2*gw1) * 128;
    const float* rpB1 = rpA1 + 128;
    #pragma unroll
    for (int l = lane; l < 128; l += 32) {
        bufA[off0 + l] = make_float2(rpA0[l], rpB0[l]);
        bufA[off1 + l] = make_float2(rpA1[l], rpB1[l]);
    }
    __syncthreads();                          // tw visibility
    fft_r4_stages_x2<0>(bufA, bufB, tw, off0, off1, lane);
    r2_final_warp(bufB, bufA, off0, lane);
    r2_final_warp(bufB, bufA, off1, lane);
    __syncwarp();
    // Hermitian unpack for both packed pairs
    #pragma unroll
    for (int p = 0; p < 2; p++) {
        int gw = p ? gw1 : gw0;
        int off = p ? off1 : off0;
        float2* oA = d_kmesh + (2*gw) * NZH;
        float2* oB = oA + NZH;
        for (int k = lane; k < 65; k += 32) {
            float2 Ck = bufA[off + k];
            float2 Cm = bufA[off + ((128 - k) & 127)];
            oA[k] = make_float2(0.5f*(Ck.x + Cm.x),  0.5f*(Ck.y - Cm.y));
            oB[k] = make_float2(0.5f*(Ck.y + Cm.y), -0.5f*(Ck.x - Cm.x));
        }
    }
}

// ---------------------------------------------------------------------------
// z inverse c2r (two-for-one): same ILP-2 structure. 512 blocks.
// ---------------------------------------------------------------------------
__global__ void k_fft_z_inv() {
    __shared__ float2 bufA[16 * 129];
    __shared__ float2 bufB[16 * 129];
    __shared__ float2 tw[128];
    int tid = threadIdx.x, lane = tid & 31, w = tid >> 5;
    int off0 = w * 129, off1 = (w + 8) * 129;
    int gw0 = blockIdx.x * 16 + w, gw1 = gw0 + 8;
    init_tw(tw, tid);
    #pragma unroll
    for (int p = 0; p < 2; p++) {
        int gw = p ? gw1 : gw0;
        int off = p ? off1 : off0;
        const float2* iA = d_kmesh + (2*gw) * NZH;
        const float2* iB = iA + NZH;
        for (int k = lane; k < 65; k += 32) {
            float2 A = iA[k], B = iB[k];
            bufA[off + k] = make_float2(A.x - B.y, A.y + B.x);
            if (k >= 1 && k <= 63)
                bufA[off + 128 - k] = make_float2(A.x + B.y, B.x - A.y);
        }
    }
    __syncthreads();                          // tw visibility
    fft_r4_stages_x2<1>(bufA, bufB, tw, off0, off1, lane);
    float* rpA0 = d_rho + (2*gw0) * 128;
    float* rpB0 = rpA0 + 128;
    float* rpA1 = d_rho + (2*gw1) * 128;
    float* rpB1 = rpA1 + 128;
    #pragma unroll
    for (int l = lane; l < 64; l += 32) {
        float2 a0 = bufB[off0 + l], b0 = bufB[off0 + l + 64];
        float2 s0 = cadd(a0, b0), d0 = csub(a0, b0);
        rpA0[l] = s0.x;  rpB0[l] = s0.y;
        rpA0[l + 64] = d0.x;  rpB0[l + 64] = d0.y;
        float2 a1 = bufB[off1 + l], b1 = bufB[off1 + l + 64];
        float2 s1 = cadd(a1, b1), d1 = csub(a1, b1);
        rpA1[l] = s1.x;  rpB1[l] = s1.y;
        rpA1[l + 64] = d1.x;  rpB1[l + 64] = d1.y;
    }
}

// ---------------------------------------------------------------------------
// y pass, HYBRID+ILP2: striped coalesced block IO, warp w owns lines w, w+8.
// 16 lines/block, 520 blocks.
// ---------------------------------------------------------------------------
template<int CONJ>
__global__ void k_fft_y() {
    __shared__ float2 bufA[16 * 129];
    __shared__ float2 bufB[16 * 129];
    __shared__ float2 tw[128];
    __shared__ int lineBase[16];
    int tid = threadIdx.x, lane = tid & 31, w = tid >> 5;
    int off0 = w * 129, off1 = (w + 8) * 129;
    init_tw(tw, tid);
    if (tid < 16) {
        int L = blockIdx.x * 16 + tid;
        int x = L / NZH, kz = L - x * NZH;
        lineBase[tid] = x * (128 * NZH) + kz;
    }
    __syncthreads();
    // striped coalesced load
    #pragma unroll
    for (int e = tid; e < 2048; e += 256) {
        int c = e & 15, l = e >> 4;
        bufA[c * 129 + l] = d_kmesh[lineBase[c] + l * NZH];
    }
    __syncthreads();
    fft_r4_stages_x2<CONJ>(bufA, bufB, tw, off0, off1, lane);
    __syncthreads();
    // striped coalesced store with fused final radix-2
    #pragma unroll
    for (int e = tid; e < 1024; e += 256) {
        int c = e & 15, l = e >> 4;
        float2 a = bufB[c * 129 + l], b = bufB[c * 129 + l + 64];
        d_kmesh[lineBase[c] + l * NZH]        = cadd(a, b);
        d_kmesh[lineBase[c] + (l + 64) * NZH] = csub(a, b);
    }
}

// ---------------------------------------------------------------------------
// Fused x pass + G(k): striped coalesced IO, warp w owns lines w, w+8.
// 16 lines/block, 520 blocks.
// ---------------------------------------------------------------------------
__global__ void k_fft_x_gmul(const float* __restrict__ cell) {
    __shared__ float2 bufA[16 * 129];
    __shared__ float2 bufB[16 * 129];
    __shared__ float2 tw[128];
    int tid = threadIdx.x, lane = tid & 31, w = tid >> 5;
    int off0 = w * 129, off1 = (w + 8) * 129;
    int L0 = blockIdx.x * 16;
    init_tw(tw, tid);
    float inv[9]; float det;
    inv3x3(cell, inv, det);
    const float TWO_PI = 6.283185307179586f;
    float b0x = TWO_PI*inv[0], b0y = TWO_PI*inv[3], b0z = TWO_PI*inv[6];
    float b1x = TWO_PI*inv[1], b1y = TWO_PI*inv[4], b1z = TWO_PI*inv[7];
    float b2x = TWO_PI*inv[2], b2y = TWO_PI*inv[5], b2z = TWO_PI*inv[8];
    float ivol = 1.0f / fabsf(det);
    int La = L0 + w, Lb = La + 8;
    int ya = La / NZH, kza = La - ya * NZH;
    int yb = Lb / NZH, kzb = Lb - yb * NZH;
    float mj0 = (float)(ya - ((ya >= 64) ? 128 : 0)), mk0 = (float)kza;
    float mj1 = (float)(yb - ((yb >= 64) ? 128 : 0)), mk1 = (float)kzb;
    // striped coalesced load
    #pragma unroll
    for (int e = tid; e < 2048; e += 256) {
        int c = e & 15, l = e >> 4;
        bufA[c * 129 + l] = d_kmesh[L0 + c + l * KLINES];
    }
    __syncthreads();
    fft_r4_stages_x2<0>(bufA, bufB, tw, off0, off1, lane);
    r2_final_warp(bufB, bufA, off0, lane);
    r2_final_warp(bufB, bufA, off1, lane);
    __syncwarp();
    // G(k)/V on both owned lines (natural order)
    #pragma unroll
    for (int p = 0; p < 2; p++) {
        int off = p ? off1 : off0;
        float mj = p ? mj1 : mj0;
        float mk = p ? mk1 : mk0;
        #pragma unroll
        for (int xk = lane; xk < 128; xk += 32) {
            float mi = (float)(xk - ((xk >= 64) ? 128 : 0));
            float kx = mi * b0x + mj * b1x + mk * b2x;
            float ky = mi * b0y + mj * b1y + mk * b2y;
            float kzv = mi * b0z + mj * b1z + mk * b2z;
            float ksq = kx*kx + ky*ky + kzv*kzv;
            float g = 0.0f;
            if (ksq != 0.0f)
                g = 12.566370614359172f / ksq * expf(-0.5f * ksq) * ivol;
            float2 v = bufA[off + xk];
            v.x *= g; v.y *= g;
            bufA[off + xk] = v;
        }
    }
    __syncwarp();
    fft_r4_stages_x2<1>(bufA, bufB, tw, off0, off1, lane);
    __syncthreads();
    // striped coalesced store with fused final radix-2
    #pragma unroll
    for (int e = tid; e < 1024; e += 256) {
        int c = e & 15, l = e >> 4;
        float2 a = bufB[c * 129 + l], b = bufB[c * 129 + l + 64];
        d_kmesh[L0 + c + l * KLINES]        = cadd(a, b);
        d_kmesh[L0 + c + (l + 64) * KLINES] = csub(a, b);
    }
}

// ---------------------------------------------------------------------------
// spline weights + stencil
// ---------------------------------------------------------------------------
__device__ __forceinline__ void spline_w4(float x, float* w) {
    float x2 = x * x, x3 = x2 * x;
    const float s = 1.0f / 48.0f;
    w[0] = ( 1.0f -  6.0f*x + 12.0f*x2 -  8.0f*x3) * s;
    w[1] = (23.0f - 30.0f*x - 12.0f*x2 + 24.0f*x3) * s;
    w[2] = (23.0f + 30.0f*x - 12.0f*x2 - 24.0f*x3) * s;
    w[3] = ( 1.0f +  6.0f*x + 12.0f*x2 +  8.0f*x3) * s;
}

__device__ __forceinline__ int atom_stencil(
    const float* __restrict__ cell, const float* __restrict__ pos, int a,
    float* wx, float* wy, float* wz, int* ix, int* iy)
{
    float inv[9]; float det;
    inv3x3(cell, inv, det);
    float p0 = pos[3*a], p1 = pos[3*a+1], p2 = pos[3*a+2];
    float r0 = (p0*inv[0] + p1*inv[3] + p2*inv[6]) * 128.0f;
    float r1 = (p0*inv[1] + p1*inv[4] + p2*inv[7]) * 128.0f;
    float r2 = (p0*inv[2] + p1*inv[5] + p2*inv[8]) * 128.0f;
    int i0 = __float2int_rd(r0);
    int i1 = __float2int_rd(r1);
    int i2 = __float2int_rd(r2);
    spline_w4(r0 - (float)i0 - 0.5f, wx);
    spline_w4(r1 - (float)i1 - 0.5f, wy);
    spline_w4(r2 - (float)i2 - 0.5f, wz);
    #pragma unroll
    for (int s = 0; s < 4; s++) {
        ix[s] = (i0 + s - 1 + 128) & 127;
        iy[s] = (i1 + s - 1 + 128) & 127;
    }
    return i2;
}

__device__ __forceinline__ void pad_quads(const float* wz, int off,
                                          float* q0, float* q1) {
    switch (off) {
    case 0: q0[0]=wz[0]; q0[1]=wz[1]; q0[2]=wz[2]; q0[3]=wz[3]; break;
    case 1: q0[1]=wz[0]; q0[2]=wz[1]; q0[3]=wz[2]; q1[0]=wz[3]; break;
    case 2: q0[2]=wz[0]; q0[3]=wz[1]; q1[0]=wz[2]; q1[1]=wz[3]; break;
    default:q0[3]=wz[0]; q1[0]=wz[1]; q1[1]=wz[2]; q1[2]=wz[3]; break;
    }
}

__device__ __forceinline__ void red4(float* p, float a, float b, float c, float d) {
    asm volatile("red.global.add.v4.f32 [%0], {%1, %2, %3, %4};"
                 :: "l"(p), "f"(a), "f"(b), "f"(c), "f"(d) : "memory");
}
__device__ __forceinline__ void red2(float* p, float a, float b) {
    asm volatile("red.global.add.v2.f32 [%0], {%1, %2};"
                 :: "l"(p), "f"(a), "f"(b) : "memory");
}
__device__ __forceinline__ void red1(float* p, float a) {
    asm volatile("red.global.add.f32 [%0], %1;"
                 :: "l"(p), "f"(a) : "memory");
}

// ---------------------------------------------------------------------------
__global__ void k_scatter(const float* __restrict__ cell,
                          const float* __restrict__ pos,
                          const float* __restrict__ chg, int n) {
    int a = blockIdx.x * blockDim.x + threadIdx.x;
    if (a >= n) return;
    float wx[4], wy[4], wz[4];
    int ix[4], iy[4];
    int i2 = atom_stencil(cell, pos, a, wx, wy, wz, ix, iy);
    float c = chg[a];
    int zlo = i2 - 1;
    if (zlo >= 0 && zlo <= 124) {
        int Q0 = zlo & ~3, off = zlo & 3;
        #pragma unroll
        for (int i = 0; i < 4; i++) {
            float cwi = c * wx[i];
            int ox = ix[i] << 14;
            #pragma unroll
            for (int j = 0; j < 4; j++) {
                float s = cwi * wy[j];
                float* p = &d_rho[ox + (iy[j] << 7) + Q0];
                switch (off) {
                case 0:
                    red4(p, s*wz[0], s*wz[1], s*wz[2], s*wz[3]);
                    break;
                case 1:
                    red4(p, 0.0f, s*wz[0], s*wz[1], s*wz[2]);
                    red1(p + 4, s*wz[3]);
                    break;
                case 2:
                    red2(p + 2, s*wz[0], s*wz[1]);
                    red2(p + 4, s*wz[2], s*wz[3]);
                    break;
                default:
                    red1(p + 3, s*wz[0]);
                    red4(p + 4, s*wz[1], s*wz[2], s*wz[3], 0.0f);
                    break;
                }
            }
        }
    } else {
        int iz[4];
        #pragma unroll
        for (int s = 0; s < 4; s++) iz[s] = (zlo + s + 128) & 127;
        #pragma unroll
        for (int i = 0; i < 4; i++) {
            float cwi = c * wx[i];
            int ox = ix[i] << 14;
            #pragma unroll
            for (int j = 0; j < 4; j++) {
                float cwij = cwi * wy[j];
                int oxy = ox + (iy[j] << 7);
                #pragma unroll
                for (int k = 0; k < 4; k++)
                    red1(&d_rho[oxy + iz[k]], cwij * wz[k]);
            }
        }
    }
}

// ---------------------------------------------------------------------------
__global__ void k_gather(const float* __restrict__ cell,
                         const float* __restrict__ pos,
                         const float* __restrict__ chg,
                         float* __restrict__ out, int n) {
    int a = blockIdx.x * blockDim.x + threadIdx.x;
    if (a >= n) return;
    float wx[4], wy[4], wz[4];
    int ix[4], iy[4];
    int i2 = atom_stencil(cell, pos, a, wx, wy, wz, ix, iy);
    float sum = 0.0f;
    int zlo = i2 - 1;
    if (zlo >= 0 && zlo <= 124) {
        int Q0 = zlo & ~3, off = zlo & 3;
        float q0[4] = {0,0,0,0}, q1[4] = {0,0,0,0};
        pad_quads(wz, off, q0, q1);
        #pragma unroll
        for (int i = 0; i < 4; i++) {
            float wi = wx[i];
            int ox = ix[i] << 14;
            #pragma unroll
            for (int j = 0; j < 4; j++) {
                const float* p = &d_rho[ox + (iy[j] << 7) + Q0];
                float4 v0 = __ldg((const float4*)p);
                float acc = v0.x*q0[0] + v0.y*q0[1] + v0.z*q0[2] + v0.w*q0[3];
                if (off) {
                    float4 v1 = __ldg((const float4*)(p + 4));
                    acc += v1.x*q1[0] + v1.y*q1[1] + v1.z*q1[2] + v1.w*q1[3];
                }
                sum += wi * wy[j] * acc;
            }
        }
    } else {
        int iz[4];
        #pragma unroll
        for (int s = 0; s < 4; s++) iz[s] = (zlo + s + 128) & 127;
        #pragma unroll
        for (int i = 0; i < 4; i++) {
            float wi = wx[i];
            int ox = ix[i] << 14;
            #pragma unroll
            for (int j = 0; j < 4; j++) {
                int oxy = ox + (iy[j] << 7);
                float acc = 0.0f;
                #pragma unroll
                for (int k = 0; k < 4; k++)
                    acc += wz[k] * d_rho[oxy + iz[k]];
                sum += wi * wy[j] * acc;
            }
        }
    }
    out[a] = sum - chg[a] * 0.7978845608028654f;
}

// ---------------------------------------------------------------------------
extern "C" void kernel_launch(void* const* d_in, const int* in_sizes, int n_in,
                              void* d_out, int out_size) {
    const float* cell = (const float*)d_in[0];
    const float* pos  = (const float*)d_in[1];
    const float* chg  = (const float*)d_in[2];
    float* out = (float*)d_out;
    int n = in_sizes[2];

    k_zero<<<2048, 256>>>();

    int ab = (n + 255) / 256;
    k_scatter<<<ab, 256>>>(cell, pos, chg, n);

    k_fft_z_fwd<<<512, 256>>>();
    k_fft_y<0><<<520, 256>>>();
    k_fft_x_gmul<<<520, 256>>>(cell);
    k_fft_y<1><<<520, 256>>>();
    k_fft_z_inv<<<512, 256>>>();

    k_gather<<<ab, 256>>>(cell, pos, chg, out, n);
}

// round 15
// speedup vs baseline: 1.0315x; 1.0315x over previous
#include <cuda_runtime.h>
#include <math.h>

#define N3 (128*128*128)
#define NZH 65                       // Hermitian half length along z
#define KLINES (128*65)              // 8320 x-lines; kmesh layout [x][kz][ky]

__device__ float2 d_kmesh[128*KLINES];   // half-spectrum mesh (8.5 MB)
__device__ float  d_rho[N3];             // dense real mesh (8 MB)

// fused-kernel dynamic smem: plane(65*129) + bufA(16*129) + bufB(16*129) + tw(128)
#define SMEM_FUSED ((65*129 + 16*129 + 16*129 + 128) * 8)

// ---------------------------------------------------------------------------
__device__ __forceinline__ float2 cadd(float2 a, float2 b){ return make_float2(a.x+b.x, a.y+b.y); }
__device__ __forceinline__ float2 csub(float2 a, float2 b){ return make_float2(a.x-b.x, a.y-b.y); }
__device__ __forceinline__ float2 cmul(float2 a, float2 w){ return make_float2(a.x*w.x-a.y*w.y, a.x*w.y+a.y*w.x); }

__device__ __forceinline__ void inv3x3(const float* __restrict__ cell,
                                       float inv[9], float& det) {
    float a = __ldg(cell+0), b = __ldg(cell+1), c = __ldg(cell+2);
    float d = __ldg(cell+3), e = __ldg(cell+4), f = __ldg(cell+5);
    float g = __ldg(cell+6), h = __ldg(cell+7), i = __ldg(cell+8);
    float C00 =  (e*i - f*h), C01 = -(d*i - f*g), C02 =  (d*h - e*g);
    float C10 = -(b*i - c*h), C11 =  (a*i - c*g), C12 = -(a*h - b*g);
    float C20 =  (b*f - c*e), C21 = -(a*f - c*d), C22 =  (a*e - b*d);
    det = a*C00 + b*C01 + c*C02;
    float idet = 1.0f / det;
    inv[0]=C00*idet; inv[1]=C10*idet; inv[2]=C20*idet;
    inv[3]=C01*idet; inv[4]=C11*idet; inv[5]=C21*idet;
    inv[6]=C02*idet; inv[7]=C12*idet; inv[8]=C22*idet;
}

__global__ void k_zero() {
    int i = blockIdx.x * blockDim.x + threadIdx.x;   // 524288 float4s (8 MB)
    ((float4*)d_rho)[i] = make_float4(0.f, 0.f, 0.f, 0.f);
}

// ---------------------------------------------------------------------------
// Radix-4 Stockham stage — per-warp line ownership; lane = butterfly index.
// ---------------------------------------------------------------------------
template<int CONJ, int S>
__device__ __forceinline__ void r4_stage(const float2* __restrict__ cur,
                                         float2* __restrict__ nxt,
                                         const float2* __restrict__ tw,
                                         int off, int t) {
    int q  = t & (S - 1);
    int sp = t - q;
    float2 a0 = cur[off + t];
    float2 a1 = cur[off + t + 32];
    float2 a2 = cur[off + t + 64];
    float2 a3 = cur[off + t + 96];
    float2 t02 = cadd(a0, a2), d02 = csub(a0, a2);
    float2 t13 = cadd(a1, a3), d13 = csub(a1, a3);
    float2 y0 = cadd(t02, t13);
    float2 y2 = csub(t02, t13);
    float2 jd;
    if (CONJ) jd = make_float2(-d13.y,  d13.x);
    else      jd = make_float2( d13.y, -d13.x);
    float2 y1 = cadd(d02, jd);
    float2 y3 = csub(d02, jd);
    float2 w1 = tw[sp], w2 = tw[2*sp], w3 = tw[3*sp];
    if (CONJ) { w1.y = -w1.y; w2.y = -w2.y; w3.y = -w3.y; }
    int o = off + t + 3*sp;
    nxt[o]       = y0;
    nxt[o + S]   = cmul(y1, w1);
    nxt[o + 2*S] = cmul(y2, w2);
    nxt[o + 3*S] = cmul(y3, w3);
}

template<int CONJ>
__device__ __forceinline__ void fft_r4_stages(float2* A, float2* B,
                                              const float2* tw,
                                              int off, int lane) {
    r4_stage<CONJ, 1 >(A, B, tw, off, lane); __syncwarp();
    r4_stage<CONJ, 4 >(B, A, tw, off, lane); __syncwarp();
    r4_stage<CONJ, 16>(A, B, tw, off, lane); __syncwarp();
    // result (pre final radix-2) in B
}

__device__ __forceinline__ void r2_final_warp(const float2* __restrict__ src,
                                              float2* __restrict__ dst,
                                              int off, int lane) {
    #pragma unroll
    for (int t = lane; t < 64; t += 32) {
        float2 a = src[off + t], b = src[off + t + 64];
        dst[off + t]      = cadd(a, b);
        dst[off + t + 64] = csub(a, b);
    }
}

__device__ __forceinline__ void init_tw(float2* tw, int tid) {
    if (tid < 128) {
        float s, c;
        sincospif((float)tid * (1.0f / 64.0f), &s, &c);
        tw[tid] = make_float2(c, -s);
    }
}

// ---------------------------------------------------------------------------
// FUSED forward: per x-plane, z-FFT (r2c two-for-one over y-pairs) into a
// shared plane P[kz][y], then y-FFT per kz, contiguous store to
// kmesh[x][kz][ky]. 128 blocks x 512 threads (16 warps).
// ---------------------------------------------------------------------------
__global__ void k_fft_zy_fwd() {
    extern __shared__ float2 sm[];
    float2* P    = sm;                       // 65 * 129
    float2* bufA = sm + 65*129;              // 16 * 129
    float2* bufB = bufA + 16*129;            // 16 * 129
    float2* tw   = bufB + 16*129;            // 128
    int tid = threadIdx.x, lane = tid & 31, w = tid >> 5;
    int off = w * 129;
    int x = blockIdx.x;
    init_tw(tw, tid);
    const float* rhoX = d_rho + x * 16384;
    __syncthreads();                         // tw visible
    // stage 1: 64 packed z-FFTs (pairs y=2p, 2p+1), 4 per warp
    for (int p = w; p < 64; p += 16) {
        const float* rA = rhoX + (2*p) * 128;
        const float* rB = rA + 128;
        #pragma unroll
        for (int l = lane; l < 128; l += 32)
            bufA[off + l] = make_float2(rA[l], rB[l]);
        __syncwarp();
        fft_r4_stages<0>(bufA, bufB, tw, off, lane);
        r2_final_warp(bufB, bufA, off, lane);
        __syncwarp();
        // Hermitian unpack into P[k][y]
        for (int k = lane; k < 65; k += 32) {
            float2 Ck = bufA[off + k];
            float2 Cm = bufA[off + ((128 - k) & 127)];
            P[k*129 + 2*p]     = make_float2(0.5f*(Ck.x + Cm.x),  0.5f*(Ck.y - Cm.y));
            P[k*129 + 2*p + 1] = make_float2(0.5f*(Ck.y + Cm.y), -0.5f*(Ck.x - Cm.x));
        }
        __syncwarp();
    }
    __syncthreads();
    // stage 2: 65 y-FFTs, contiguous store
    float2* kX = d_kmesh + x * KLINES;
    for (int L = w; L < 65; L += 16) {
        #pragma unroll
        for (int l = lane; l < 128; l += 32)
            bufA[off + l] = P[L*129 + l];
        __syncwarp();
        fft_r4_stages<0>(bufA, bufB, tw, off, lane);
        #pragma unroll
        for (int t = lane; t < 64; t += 32) {
            float2 a = bufB[off + t], b = bufB[off + t + 64];
            kX[L*128 + t]      = cadd(a, b);
            kX[L*128 + t + 64] = csub(a, b);
        }
        __syncwarp();
    }
}

// ---------------------------------------------------------------------------
// FUSED inverse: per x-plane, inverse y-FFT per kz into P[kz][y], then
// inverse z c2r (two-for-one) writing the real plane. 128 blocks x 512.
// ---------------------------------------------------------------------------
__global__ void k_fft_yz_inv() {
    extern __shared__ float2 sm[];
    float2* P    = sm;
    float2* bufA = sm + 65*129;
    float2* bufB = bufA + 16*129;
    float2* tw   = bufB + 16*129;
    int tid = threadIdx.x, lane = tid & 31, w = tid >> 5;
    int off = w * 129;
    int x = blockIdx.x;
    init_tw(tw, tid);
    const float2* kX = d_kmesh + x * KLINES;
    __syncthreads();                         // tw visible
    // stage 1: 65 inverse y-FFTs into P[kz][y]
    for (int L = w; L < 65; L += 16) {
        #pragma unroll
        for (int l = lane; l < 128; l += 32)
            bufA[off + l] = kX[L*128 + l];
        __syncwarp();
        fft_r4_stages<1>(bufA, bufB, tw, off, lane);
        #pragma unroll
        for (int t = lane; t < 64; t += 32) {
            float2 a = bufB[off + t], b = bufB[off + t + 64];
            P[L*129 + t]      = cadd(a, b);
            P[L*129 + t + 64] = csub(a, b);
        }
        __syncwarp();
    }
    __syncthreads();
    // stage 2: 64 packed inverse z c2r FFTs (pairs y=2p, 2p+1)
    float* rhoX = d_rho + x * 16384;
    for (int p = w; p < 64; p += 16) {
        int y0 = 2*p, y1 = 2*p + 1;
        for (int k = lane; k < 65; k += 32) {
            float2 A = P[k*129 + y0], B = P[k*129 + y1];
            bufA[off + k] = make_float2(A.x - B.y, A.y + B.x);
            if (k >= 1 && k <= 63)
                bufA[off + 128 - k] = make_float2(A.x + B.y, B.x - A.y);
        }
        __syncwarp();
        fft_r4_stages<1>(bufA, bufB, tw, off, lane);
        float* rA = rhoX + y0 * 128;
        float* rB = rA + 128;
        #pragma unroll
        for (int l = lane; l < 64; l += 32) {
            float2 a = bufB[off + l], b = bufB[off + l + 64];
            float2 su = cadd(a, b), df = csub(a, b);
            rA[l]      = su.x;
            rB[l]      = su.y;
            rA[l + 64] = df.x;
            rB[l + 64] = df.y;
        }
        __syncwarp();
    }
}

// ---------------------------------------------------------------------------
// Fused x pass + G(k): striped coalesced IO, warp w owns line L0+w.
// kmesh layout [x][kz][ky]: line L -> ky = L & 127, kz = L >> 7. 1040 blocks.
// ---------------------------------------------------------------------------
__global__ void k_fft_x_gmul(const float* __restrict__ cell) {
    __shared__ float2 bufA[8 * 129];
    __shared__ float2 bufB[8 * 129];
    __shared__ float2 tw[128];
    int tid = threadIdx.x, lane = tid & 31, w = tid >> 5;
    int off = w * 129;
    int L0 = blockIdx.x * 8;
    init_tw(tw, tid);
    float inv[9]; float det;
    inv3x3(cell, inv, det);
    const float TWO_PI = 6.283185307179586f;
    float b0x = TWO_PI*inv[0], b0y = TWO_PI*inv[3], b0z = TWO_PI*inv[6];
    float b1x = TWO_PI*inv[1], b1y = TWO_PI*inv[4], b1z = TWO_PI*inv[7];
    float b2x = TWO_PI*inv[2], b2y = TWO_PI*inv[5], b2z = TWO_PI*inv[8];
    float ivol = 1.0f / fabsf(det);
    int L = L0 + w;
    int ky = L & 127, kz = L >> 7;
    float mj = (float)(ky - ((ky >= 64) ? 128 : 0));
    float mk = (float)kz;
    // striped coalesced load
    #pragma unroll
    for (int e = tid; e < 1024; e += 256) {
        int c = e & 7, l = e >> 3;
        bufA[c * 129 + l] = d_kmesh[L0 + c + l * KLINES];
    }
    __syncthreads();
    fft_r4_stages<0>(bufA, bufB, tw, off, lane);
    r2_final_warp(bufB, bufA, off, lane);
    __syncwarp();
    // G(k)/V on own line in natural order
    #pragma unroll
    for (int xk = lane; xk < 128; xk += 32) {
        float mi = (float)(xk - ((xk >= 64) ? 128 : 0));
        float kx = mi * b0x + mj * b1x + mk * b2x;
        float kyv = mi * b0y + mj * b1y + mk * b2y;
        float kzv = mi * b0z + mj * b1z + mk * b2z;
        float ksq = kx*kx + kyv*kyv + kzv*kzv;
        float g = 0.0f;
        if (ksq != 0.0f)
            g = 12.566370614359172f / ksq * expf(-0.5f * ksq) * ivol;
        float2 v = bufA[off + xk];
        v.x *= g; v.y *= g;
        bufA[off + xk] = v;
    }
    __syncwarp();
    fft_r4_stages<1>(bufA, bufB, tw, off, lane);
    __syncthreads();
    // striped coalesced store with fused final radix-2
    #pragma unroll
    for (int e = tid; e < 512; e += 256) {
        int c = e & 7, l = e >> 3;
        float2 a = bufB[c * 129 + l], b = bufB[c * 129 + l + 64];
        d_kmesh[L0 + c + l * KLINES]        = cadd(a, b);
        d_kmesh[L0 + c + (l + 64) * KLINES] = csub(a, b);
    }
}

// ---------------------------------------------------------------------------
// spline weights + stencil
// ---------------------------------------------------------------------------
__device__ __forceinline__ void spline_w4(float x, float* w) {
    float x2 = x * x, x3 = x2 * x;
    const float s = 1.0f / 48.0f;
    w[0] = ( 1.0f -  6.0f*x + 12.0f*x2 -  8.0f*x3) * s;
    w[1] = (23.0f - 30.0f*x - 12.0f*x2 + 24.0f*x3) * s;
    w[2] = (23.0f + 30.0f*x - 12.0f*x2 - 24.0f*x3) * s;
    w[3] = ( 1.0f +  6.0f*x + 12.0f*x2 +  8.0f*x3) * s;
}

__device__ __forceinline__ int atom_stencil(
    const float* __restrict__ cell, const float* __restrict__ pos, int a,
    float* wx, float* wy, float* wz, int* ix, int* iy)
{
    float inv[9]; float det;
    inv3x3(cell, inv, det);
    float p0 = pos[3*a], p1 = pos[3*a+1], p2 = pos[3*a+2];
    float r0 = (p0*inv[0] + p1*inv[3] + p2*inv[6]) * 128.0f;
    float r1 = (p0*inv[1] + p1*inv[4] + p2*inv[7]) * 128.0f;
    float r2 = (p0*inv[2] + p1*inv[5] + p2*inv[8]) * 128.0f;
    int i0 = __float2int_rd(r0);
    int i1 = __float2int_rd(r1);
    int i2 = __float2int_rd(r2);
    spline_w4(r0 - (float)i0 - 0.5f, wx);
    spline_w4(r1 - (float)i1 - 0.5f, wy);
    spline_w4(r2 - (float)i2 - 0.5f, wz);
    #pragma unroll
    for (int s = 0; s < 4; s++) {
        ix[s] = (i0 + s - 1 + 128) & 127;
        iy[s] = (i1 + s - 1 + 128) & 127;
    }
    return i2;
}

__device__ __forceinline__ void pad_quads(const float* wz, int off,
                                          float* q0, float* q1) {
    switch (off) {
    case 0: q0[0]=wz[0]; q0[1]=wz[1]; q0[2]=wz[2]; q0[3]=wz[3]; break;
    case 1: q0[1]=wz[0]; q0[2]=wz[1]; q0[3]=wz[2]; q1[0]=wz[3]; break;
    case 2: q0[2]=wz[0]; q0[3]=wz[1]; q1[0]=wz[2]; q1[1]=wz[3]; break;
    default:q0[3]=wz[0]; q1[0]=wz[1]; q1[1]=wz[2]; q1[2]=wz[3]; break;
    }
}

__device__ __forceinline__ void red4(float* p, float a, float b, float c, float d) {
    asm volatile("red.global.add.v4.f32 [%0], {%1, %2, %3, %4};"
                 :: "l"(p), "f"(a), "f"(b), "f"(c), "f"(d) : "memory");
}
__device__ __forceinline__ void red2(float* p, float a, float b) {
    asm volatile("red.global.add.v2.f32 [%0], {%1, %2};"
                 :: "l"(p), "f"(a), "f"(b) : "memory");
}
__device__ __forceinline__ void red1(float* p, float a) {
    asm volatile("red.global.add.f32 [%0], %1;"
                 :: "l"(p), "f"(a) : "memory");
}

// ---------------------------------------------------------------------------
__global__ void k_scatter(const float* __restrict__ cell,
                          const float* __restrict__ pos,
                          const float* __restrict__ chg, int n) {
    int a = blockIdx.x * blockDim.x + threadIdx.x;
    if (a >= n) return;
    float wx[4], wy[4], wz[4];
    int ix[4], iy[4];
    int i2 = atom_stencil(cell, pos, a, wx, wy, wz, ix, iy);
    float c = chg[a];
    int zlo = i2 - 1;
    if (zlo >= 0 && zlo <= 124) {
        int Q0 = zlo & ~3, off = zlo & 3;
        #pragma unroll
        for (int i = 0; i < 4; i++) {
            float cwi = c * wx[i];
            int ox = ix[i] << 14;
            #pragma unroll
            for (int j = 0; j < 4; j++) {
                float s = cwi * wy[j];
                float* p = &d_rho[ox + (iy[j] << 7) + Q0];
                switch (off) {
                case 0:
                    red4(p, s*wz[0], s*wz[1], s*wz[2], s*wz[3]);
                    break;
                case 1:
                    red4(p, 0.0f, s*wz[0], s*wz[1], s*wz[2]);
                    red1(p + 4, s*wz[3]);
                    break;
                case 2:
                    red2(p + 2, s*wz[0], s*wz[1]);
                    red2(p + 4, s*wz[2], s*wz[3]);
                    break;
                default:
                    red1(p + 3, s*wz[0]);
                    red4(p + 4, s*wz[1], s*wz[2], s*wz[3], 0.0f);
                    break;
                }
            }
        }
    } else {
        int iz[4];
        #pragma unroll
        for (int s = 0; s < 4; s++) iz[s] = (zlo + s + 128) & 127;
        #pragma unroll
        for (int i = 0; i < 4; i++) {
            float cwi = c * wx[i];
            int ox = ix[i] << 14;
            #pragma unroll
            for (int j = 0; j < 4; j++) {
                float cwij = cwi * wy[j];
                int oxy = ox + (iy[j] << 7);
                #pragma unroll
                for (int k = 0; k < 4; k++)
                    red1(&d_rho[oxy + iz[k]], cwij * wz[k]);
            }
        }
    }
}

// ---------------------------------------------------------------------------
__global__ void k_gather(const float* __restrict__ cell,
                         const float* __restrict__ pos,
                         const float* __restrict__ chg,
                         float* __restrict__ out, int n) {
    int a = blockIdx.x * blockDim.x + threadIdx.x;
    if (a >= n) return;
    float wx[4], wy[4], wz[4];
    int ix[4], iy[4];
    int i2 = atom_stencil(cell, pos, a, wx, wy, wz, ix, iy);
    float sum = 0.0f;
    int zlo = i2 - 1;
    if (zlo >= 0 && zlo <= 124) {
        int Q0 = zlo & ~3, off = zlo & 3;
        float q0[4] = {0,0,0,0}, q1[4] = {0,0,0,0};
        pad_quads(wz, off, q0, q1);
        #pragma unroll
        for (int i = 0; i < 4; i++) {
            float wi = wx[i];
            int ox = ix[i] << 14;
            #pragma unroll
            for (int j = 0; j < 4; j++) {
                const float* p = &d_rho[ox + (iy[j] << 7) + Q0];
                float4 v0 = __ldg((const float4*)p);
                float acc = v0.x*q0[0] + v0.y*q0[1] + v0.z*q0[2] + v0.w*q0[3];
                if (off) {
                    float4 v1 = __ldg((const float4*)(p + 4));
                    acc += v1.x*q1[0] + v1.y*q1[1] + v1.z*q1[2] + v1.w*q1[3];
                }
                sum += wi * wy[j] * acc;
            }
        }
    } else {
        int iz[4];
        #pragma unroll
        for (int s = 0; s < 4; s++) iz[s] = (zlo + s + 128) & 127;
        #pragma unroll
        for (int i = 0; i < 4; i++) {
            float wi = wx[i];
            int ox = ix[i] << 14;
            #pragma unroll
            for (int j = 0; j < 4; j++) {
                int oxy = ox + (iy[j] << 7);
                float acc = 0.0f;
                #pragma unroll
                for (int k = 0; k < 4; k++)
                    acc += wz[k] * d_rho[oxy + iz[k]];
                sum += wi * wy[j] * acc;
            }
        }
    }
    out[a] = sum - chg[a] * 0.7978845608028654f;
}

// ---------------------------------------------------------------------------
extern "C" void kernel_launch(void* const* d_in, const int* in_sizes, int n_in,
                              void* d_out, int out_size) {
    const float* cell = (const float*)d_in[0];
    const float* pos  = (const float*)d_in[1];
    const float* chg  = (const float*)d_in[2];
    float* out = (float*)d_out;
    int n = in_sizes[2];

    cudaFuncSetAttribute(k_fft_zy_fwd,
        cudaFuncAttributeMaxDynamicSharedMemorySize, SMEM_FUSED);
    cudaFuncSetAttribute(k_fft_yz_inv,
        cudaFuncAttributeMaxDynamicSharedMemorySize, SMEM_FUSED);

    k_zero<<<2048, 256>>>();

    int ab = (n + 255) / 256;
    k_scatter<<<ab, 256>>>(cell, pos, chg, n);

    k_fft_zy_fwd<<<128, 512, SMEM_FUSED>>>();
    k_fft_x_gmul<<<1040, 256>>>(cell);
    k_fft_yz_inv<<<128, 512, SMEM_FUSED>>>();

    k_gather<<<ab, 256>>>(cell, pos, chg, out, n);
}

// round 16
// speedup vs baseline: 1.0338x; 1.0023x over previous
#include <cuda_runtime.h>
#include <math.h>

#define N3 (128*128*128)
#define NZH 65                       // Hermitian half length along z
#define KLINES (128*65)              // 8320 x-lines; kmesh layout [x][kz][ky]

__device__ float2 d_kmesh[128*KLINES];   // half-spectrum mesh (8.5 MB)
__device__ float  d_rho[N3];             // dense real mesh (8 MB)

// fused-kernel dynamic smem: plane(65*129) + bufA(32*129) + bufB(32*129) + tw(128)
#define SMEM_FUSED ((65*129 + 32*129 + 32*129 + 128) * 8)

// ---------------------------------------------------------------------------
__device__ __forceinline__ float2 cadd(float2 a, float2 b){ return make_float2(a.x+b.x, a.y+b.y); }
__device__ __forceinline__ float2 csub(float2 a, float2 b){ return make_float2(a.x-b.x, a.y-b.y); }
__device__ __forceinline__ float2 cmul(float2 a, float2 w){ return make_float2(a.x*w.x-a.y*w.y, a.x*w.y+a.y*w.x); }

__device__ __forceinline__ void inv3x3(const float* __restrict__ cell,
                                       float inv[9], float& det) {
    float a = __ldg(cell+0), b = __ldg(cell+1), c = __ldg(cell+2);
    float d = __ldg(cell+3), e = __ldg(cell+4), f = __ldg(cell+5);
    float g = __ldg(cell+6), h = __ldg(cell+7), i = __ldg(cell+8);
    float C00 =  (e*i - f*h), C01 = -(d*i - f*g), C02 =  (d*h - e*g);
    float C10 = -(b*i - c*h), C11 =  (a*i - c*g), C12 = -(a*h - b*g);
    float C20 =  (b*f - c*e), C21 = -(a*f - c*d), C22 =  (a*e - b*d);
    det = a*C00 + b*C01 + c*C02;
    float idet = 1.0f / det;
    inv[0]=C00*idet; inv[1]=C10*idet; inv[2]=C20*idet;
    inv[3]=C01*idet; inv[4]=C11*idet; inv[5]=C21*idet;
    inv[6]=C02*idet; inv[7]=C12*idet; inv[8]=C22*idet;
}

__global__ void k_zero() {
    int i = blockIdx.x * blockDim.x + threadIdx.x;   // 524288 float4s (8 MB)
    ((float4*)d_rho)[i] = make_float4(0.f, 0.f, 0.f, 0.f);
}

// ---------------------------------------------------------------------------
// Radix-4 Stockham stage — per-warp line ownership; lane = butterfly index.
// ---------------------------------------------------------------------------
template<int CONJ, int S>
__device__ __forceinline__ void r4_stage(const float2* __restrict__ cur,
                                         float2* __restrict__ nxt,
                                         const float2* __restrict__ tw,
                                         int off, int t) {
    int q  = t & (S - 1);
    int sp = t - q;
    float2 a0 = cur[off + t];
    float2 a1 = cur[off + t + 32];
    float2 a2 = cur[off + t + 64];
    float2 a3 = cur[off + t + 96];
    float2 t02 = cadd(a0, a2), d02 = csub(a0, a2);
    float2 t13 = cadd(a1, a3), d13 = csub(a1, a3);
    float2 y0 = cadd(t02, t13);
    float2 y2 = csub(t02, t13);
    float2 jd;
    if (CONJ) jd = make_float2(-d13.y,  d13.x);
    else      jd = make_float2( d13.y, -d13.x);
    float2 y1 = cadd(d02, jd);
    float2 y3 = csub(d02, jd);
    float2 w1 = tw[sp], w2 = tw[2*sp], w3 = tw[3*sp];
    if (CONJ) { w1.y = -w1.y; w2.y = -w2.y; w3.y = -w3.y; }
    int o = off + t + 3*sp;
    nxt[o]       = y0;
    nxt[o + S]   = cmul(y1, w1);
    nxt[o + 2*S] = cmul(y2, w2);
    nxt[o + 3*S] = cmul(y3, w3);
}

template<int CONJ>
__device__ __forceinline__ void fft_r4_stages(float2* A, float2* B,
                                              const float2* tw,
                                              int off, int lane) {
    r4_stage<CONJ, 1 >(A, B, tw, off, lane); __syncwarp();
    r4_stage<CONJ, 4 >(B, A, tw, off, lane); __syncwarp();
    r4_stage<CONJ, 16>(A, B, tw, off, lane); __syncwarp();
    // result (pre final radix-2) in B
}

__device__ __forceinline__ void r2_final_warp(const float2* __restrict__ src,
                                              float2* __restrict__ dst,
                                              int off, int lane) {
    #pragma unroll
    for (int t = lane; t < 64; t += 32) {
        float2 a = src[off + t], b = src[off + t + 64];
        dst[off + t]      = cadd(a, b);
        dst[off + t + 64] = csub(a, b);
    }
}

__device__ __forceinline__ void init_tw(float2* tw, int tid) {
    if (tid < 128) {
        float s, c;
        sincospif((float)tid * (1.0f / 64.0f), &s, &c);
        tw[tid] = make_float2(c, -s);
    }
}

// ---------------------------------------------------------------------------
// FUSED forward: per x-plane, z-FFT (r2c two-for-one over y-pairs) into a
// shared plane P[kz][y], then y-FFT per kz, contiguous store to
// kmesh[x][kz][ky]. 128 blocks x 1024 threads (32 warps).
// ---------------------------------------------------------------------------
__global__ __launch_bounds__(1024, 1) void k_fft_zy_fwd() {
    extern __shared__ float2 sm[];
    float2* P    = sm;                       // 65 * 129
    float2* bufA = sm + 65*129;              // 32 * 129
    float2* bufB = bufA + 32*129;            // 32 * 129
    float2* tw   = bufB + 32*129;            // 128
    int tid = threadIdx.x, lane = tid & 31, w = tid >> 5;
    int off = w * 129;
    int x = blockIdx.x;
    init_tw(tw, tid);
    const float* rhoX = d_rho + x * 16384;
    __syncthreads();                         // tw visible
    // stage 1: 64 packed z-FFTs (pairs y=2p, 2p+1), 2 per warp
    for (int p = w; p < 64; p += 32) {
        const float* rA = rhoX + (2*p) * 128;
        const float* rB = rA + 128;
        #pragma unroll
        for (int l = lane; l < 128; l += 32)
            bufA[off + l] = make_float2(rA[l], rB[l]);
        __syncwarp();
        fft_r4_stages<0>(bufA, bufB, tw, off, lane);
        r2_final_warp(bufB, bufA, off, lane);
        __syncwarp();
        // Hermitian unpack into P[k][y]
        for (int k = lane; k < 65; k += 32) {
            float2 Ck = bufA[off + k];
            float2 Cm = bufA[off + ((128 - k) & 127)];
            P[k*129 + 2*p]     = make_float2(0.5f*(Ck.x + Cm.x),  0.5f*(Ck.y - Cm.y));
            P[k*129 + 2*p + 1] = make_float2(0.5f*(Ck.y + Cm.y), -0.5f*(Ck.x - Cm.x));
        }
        __syncwarp();
    }
    __syncthreads();
    // stage 2: 65 y-FFTs, contiguous store
    float2* kX = d_kmesh + x * KLINES;
    for (int L = w; L < 65; L += 32) {
        #pragma unroll
        for (int l = lane; l < 128; l += 32)
            bufA[off + l] = P[L*129 + l];
        __syncwarp();
        fft_r4_stages<0>(bufA, bufB, tw, off, lane);
        #pragma unroll
        for (int t = lane; t < 64; t += 32) {
            float2 a = bufB[off + t], b = bufB[off + t + 64];
            kX[L*128 + t]      = cadd(a, b);
            kX[L*128 + t + 64] = csub(a, b);
        }
        __syncwarp();
    }
}

// ---------------------------------------------------------------------------
// FUSED inverse: per x-plane, inverse y-FFT per kz into P[kz][y], then
// inverse z c2r (two-for-one) writing the real plane. 128 blocks x 1024.
// ---------------------------------------------------------------------------
__global__ __launch_bounds__(1024, 1) void k_fft_yz_inv() {
    extern __shared__ float2 sm[];
    float2* P    = sm;
    float2* bufA = sm + 65*129;
    float2* bufB = bufA + 32*129;
    float2* tw   = bufB + 32*129;
    int tid = threadIdx.x, lane = tid & 31, w = tid >> 5;
    int off = w * 129;
    int x = blockIdx.x;
    init_tw(tw, tid);
    const float2* kX = d_kmesh + x * KLINES;
    __syncthreads();                         // tw visible
    // stage 1: 65 inverse y-FFTs into P[kz][y]
    for (int L = w; L < 65; L += 32) {
        #pragma unroll
        for (int l = lane; l < 128; l += 32)
            bufA[off + l] = kX[L*128 + l];
        __syncwarp();
        fft_r4_stages<1>(bufA, bufB, tw, off, lane);
        #pragma unroll
        for (int t = lane; t < 64; t += 32) {
            float2 a = bufB[off + t], b = bufB[off + t + 64];
            P[L*129 + t]      = cadd(a, b);
            P[L*129 + t + 64] = csub(a, b);
        }
        __syncwarp();
    }
    __syncthreads();
    // stage 2: 64 packed inverse z c2r FFTs (pairs y=2p, 2p+1)
    float* rhoX = d_rho + x * 16384;
    for (int p = w; p < 64; p += 32) {
        int y0 = 2*p, y1 = 2*p + 1;
        for (int k = lane; k < 65; k += 32) {
            float2 A = P[k*129 + y0], B = P[k*129 + y1];
            bufA[off + k] = make_float2(A.x - B.y, A.y + B.x);
            if (k >= 1 && k <= 63)
                bufA[off + 128 - k] = make_float2(A.x + B.y, B.x - A.y);
        }
        __syncwarp();
        fft_r4_stages<1>(bufA, bufB, tw, off, lane);
        float* rA = rhoX + y0 * 128;
        float* rB = rA + 128;
        #pragma unroll
        for (int l = lane; l < 64; l += 32) {
            float2 a = bufB[off + l], b = bufB[off + l + 64];
            float2 su = cadd(a, b), df = csub(a, b);
            rA[l]      = su.x;
            rB[l]      = su.y;
            rA[l + 64] = df.x;
            rB[l + 64] = df.y;
        }
        __syncwarp();
    }
}

// ---------------------------------------------------------------------------
// Fused x pass + G(k): striped coalesced IO, warp w owns line L0+w.
// G coefficients live in shared (not registers) to cut register pressure.
// kmesh layout [x][kz][ky]: line L -> ky = L & 127, kz = L >> 7. 1040 blocks.
// ---------------------------------------------------------------------------
__global__ __launch_bounds__(256, 7) void k_fft_x_gmul(const float* __restrict__ cell) {
    __shared__ float2 bufA[8 * 129];
    __shared__ float2 bufB[8 * 129];
    __shared__ float2 tw[128];
    __shared__ float gc[10];                 // b0x..b2z (row-major), ivol
    int tid = threadIdx.x, lane = tid & 31, w = tid >> 5;
    int off = w * 129;
    int L0 = blockIdx.x * 8;
    init_tw(tw, tid);
    if (tid == 0) {
        float inv[9]; float det;
        inv3x3(cell, inv, det);
        const float TWO_PI = 6.283185307179586f;
        // gc[3*r + s] = Brec[r][s] = 2*pi*inv[s][r]
        gc[0] = TWO_PI*inv[0]; gc[1] = TWO_PI*inv[3]; gc[2] = TWO_PI*inv[6];
        gc[3] = TWO_PI*inv[1]; gc[4] = TWO_PI*inv[4]; gc[5] = TWO_PI*inv[7];
        gc[6] = TWO_PI*inv[2]; gc[7] = TWO_PI*inv[5]; gc[8] = TWO_PI*inv[8];
        gc[9] = 1.0f / fabsf(det);
    }
    int L = L0 + w;
    int ky = L & 127, kz = L >> 7;
    float mj = (float)(ky - ((ky >= 64) ? 128 : 0));
    float mk = (float)kz;
    // striped coalesced load
    #pragma unroll
    for (int e = tid; e < 1024; e += 256) {
        int c = e & 7, l = e >> 3;
        bufA[c * 129 + l] = d_kmesh[L0 + c + l * KLINES];
    }
    __syncthreads();                         // tw + gc + tiles visible
    fft_r4_stages<0>(bufA, bufB, tw, off, lane);
    r2_final_warp(bufB, bufA, off, lane);
    __syncwarp();
    // G(k)/V on own line in natural order (coefficients broadcast from shared)
    {
        float jx = mj * gc[3] + mk * gc[6];
        float jy = mj * gc[4] + mk * gc[7];
        float jz = mj * gc[5] + mk * gc[8];
        float ivol = gc[9];
        #pragma unroll
        for (int xk = lane; xk < 128; xk += 32) {
            float mi = (float)(xk - ((xk >= 64) ? 128 : 0));
            float kx = mi * gc[0] + jx;
            float kyv = mi * gc[1] + jy;
            float kzv = mi * gc[2] + jz;
            float ksq = kx*kx + kyv*kyv + kzv*kzv;
            float g = 0.0f;
            if (ksq != 0.0f)
                g = 12.566370614359172f / ksq * expf(-0.5f * ksq) * ivol;
            float2 v = bufA[off + xk];
            v.x *= g; v.y *= g;
            bufA[off + xk] = v;
        }
    }
    __syncwarp();
    fft_r4_stages<1>(bufA, bufB, tw, off, lane);
    __syncthreads();
    // striped coalesced store with fused final radix-2
    #pragma unroll
    for (int e = tid; e < 512; e += 256) {
        int c = e & 7, l = e >> 3;
        float2 a = bufB[c * 129 + l], b = bufB[c * 129 + l + 64];
        d_kmesh[L0 + c + l * KLINES]        = cadd(a, b);
        d_kmesh[L0 + c + (l + 64) * KLINES] = csub(a, b);
    }
}

// ---------------------------------------------------------------------------
// spline weights + stencil
// ---------------------------------------------------------------------------
__device__ __forceinline__ void spline_w4(float x, float* w) {
    float x2 = x * x, x3 = x2 * x;
    const float s = 1.0f / 48.0f;
    w[0] = ( 1.0f -  6.0f*x + 12.0f*x2 -  8.0f*x3) * s;
    w[1] = (23.0f - 30.0f*x - 12.0f*x2 + 24.0f*x3) * s;
    w[2] = (23.0f + 30.0f*x - 12.0f*x2 - 24.0f*x3) * s;
    w[3] = ( 1.0f +  6.0f*x + 12.0f*x2 +  8.0f*x3) * s;
}

__device__ __forceinline__ int atom_stencil(
    const float* __restrict__ cell, const float* __restrict__ pos, int a,
    float* wx, float* wy, float* wz, int* ix, int* iy)
{
    float inv[9]; float det;
    inv3x3(cell, inv, det);
    float p0 = pos[3*a], p1 = pos[3*a+1], p2 = pos[3*a+2];
    float r0 = (p0*inv[0] + p1*inv[3] + p2*inv[6]) * 128.0f;
    float r1 = (p0*inv[1] + p1*inv[4] + p2*inv[7]) * 128.0f;
    float r2 = (p0*inv[2] + p1*inv[5] + p2*inv[8]) * 128.0f;
    int i0 = __float2int_rd(r0);
    int i1 = __float2int_rd(r1);
    int i2 = __float2int_rd(r2);
    spline_w4(r0 - (float)i0 - 0.5f, wx);
    spline_w4(r1 - (float)i1 - 0.5f, wy);
    spline_w4(r2 - (float)i2 - 0.5f, wz);
    #pragma unroll
    for (int s = 0; s < 4; s++) {
        ix[s] = (i0 + s - 1 + 128) & 127;
        iy[s] = (i1 + s - 1 + 128) & 127;
    }
    return i2;
}

__device__ __forceinline__ void pad_quads(const float* wz, int off,
                                          float* q0, float* q1) {
    switch (off) {
    case 0: q0[0]=wz[0]; q0[1]=wz[1]; q0[2]=wz[2]; q0[3]=wz[3]; break;
    case 1: q0[1]=wz[0]; q0[2]=wz[1]; q0[3]=wz[2]; q1[0]=wz[3]; break;
    case 2: q0[2]=wz[0]; q0[3]=wz[1]; q1[0]=wz[2]; q1[1]=wz[3]; break;
    default:q0[3]=wz[0]; q1[0]=wz[1]; q1[1]=wz[2]; q1[2]=wz[3]; break;
    }
}

__device__ __forceinline__ void red4(float* p, float a, float b, float c, float d) {
    asm volatile("red.global.add.v4.f32 [%0], {%1, %2, %3, %4};"
                 :: "l"(p), "f"(a), "f"(b), "f"(c), "f"(d) : "memory");
}
__device__ __forceinline__ void red2(float* p, float a, float b) {
    asm volatile("red.global.add.v2.f32 [%0], {%1, %2};"
                 :: "l"(p), "f"(a), "f"(b) : "memory");
}
__device__ __forceinline__ void red1(float* p, float a) {
    asm volatile("red.global.add.f32 [%0], %1;"
                 :: "l"(p), "f"(a) : "memory");
}

// ---------------------------------------------------------------------------
__global__ void k_scatter(const float* __restrict__ cell,
                          const float* __restrict__ pos,
                          const float* __restrict__ chg, int n) {
    int a = blockIdx.x * blockDim.x + threadIdx.x;
    if (a >= n) return;
    float wx[4], wy[4], wz[4];
    int ix[4], iy[4];
    int i2 = atom_stencil(cell, pos, a, wx, wy, wz, ix, iy);
    float c = chg[a];
    int zlo = i2 - 1;
    if (zlo >= 0 && zlo <= 124) {
        int Q0 = zlo & ~3, off = zlo & 3;
        #pragma unroll
        for (int i = 0; i < 4; i++) {
            float cwi = c * wx[i];
            int ox = ix[i] << 14;
            #pragma unroll
            for (int j = 0; j < 4; j++) {
                float s = cwi * wy[j];
                float* p = &d_rho[ox + (iy[j] << 7) + Q0];
                switch (off) {
                case 0:
                    red4(p, s*wz[0], s*wz[1], s*wz[2], s*wz[3]);
                    break;
                case 1:
                    red4(p, 0.0f, s*wz[0], s*wz[1], s*wz[2]);
                    red1(p + 4, s*wz[3]);
                    break;
                case 2:
                    red2(p + 2, s*wz[0], s*wz[1]);
                    red2(p + 4, s*wz[2], s*wz[3]);
                    break;
                default:
                    red1(p + 3, s*wz[0]);
                    red4(p + 4, s*wz[1], s*wz[2], s*wz[3], 0.0f);
                    break;
                }
            }
        }
    } else {
        int iz[4];
        #pragma unroll
        for (int s = 0; s < 4; s++) iz[s] = (zlo + s + 128) & 127;
        #pragma unroll
        for (int i = 0; i < 4; i++) {
            float cwi = c * wx[i];
            int ox = ix[i] << 14;
            #pragma unroll
            for (int j = 0; j < 4; j++) {
                float cwij = cwi * wy[j];
                int oxy = ox + (iy[j] << 7);
                #pragma unroll
                for (int k = 0; k < 4; k++)
                    red1(&d_rho[oxy + iz[k]], cwij * wz[k]);
            }
        }
    }
}

// ---------------------------------------------------------------------------
__global__ void k_gather(const float* __restrict__ cell,
                         const float* __restrict__ pos,
                         const float* __restrict__ chg,
                         float* __restrict__ out, int n) {
    int a = blockIdx.x * blockDim.x + threadIdx.x;
    if (a >= n) return;
    float wx[4], wy[4], wz[4];
    int ix[4], iy[4];
    int i2 = atom_stencil(cell, pos, a, wx, wy, wz, ix, iy);
    float sum = 0.0f;
    int zlo = i2 - 1;
    if (zlo >= 0 && zlo <= 124) {
        int Q0 = zlo & ~3, off = zlo & 3;
        float q0[4] = {0,0,0,0}, q1[4] = {0,0,0,0};
        pad_quads(wz, off, q0, q1);
        #pragma unroll
        for (int i = 0; i < 4; i++) {
            float wi = wx[i];
            int ox = ix[i] << 14;
            #pragma unroll
            for (int j = 0; j < 4; j++) {
                const float* p = &d_rho[ox + (iy[j] << 7) + Q0];
                float4 v0 = __ldg((const float4*)p);
                float acc = v0.x*q0[0] + v0.y*q0[1] + v0.z*q0[2] + v0.w*q0[3];
                if (off) {
                    float4 v1 = __ldg((const float4*)(p + 4));
                    acc += v1.x*q1[0] + v1.y*q1[1] + v1.z*q1[2] + v1.w*q1[3];
                }
                sum += wi * wy[j] * acc;
            }
        }
    } else {
        int iz[4];
        #pragma unroll
        for (int s = 0; s < 4; s++) iz[s] = (zlo + s + 128) & 127;
        #pragma unroll
        for (int i = 0; i < 4; i++) {
            float wi = wx[i];
            int ox = ix[i] << 14;
            #pragma unroll
            for (int j = 0; j < 4; j++) {
                int oxy = ox + (iy[j] << 7);
                float acc = 0.0f;
                #pragma unroll
                for (int k = 0; k < 4; k++)
                    acc += wz[k] * d_rho[oxy + iz[k]];
                sum += wi * wy[j] * acc;
            }
        }
    }
    out[a] = sum - chg[a] * 0.7978845608028654f;
}

// ---------------------------------------------------------------------------
extern "C" void kernel_launch(void* const* d_in, const int* in_sizes, int n_in,
                              void* d_out, int out_size) {
    const float* cell = (const float*)d_in[0];
    const float* pos  = (const float*)d_in[1];
    const float* chg  = (const float*)d_in[2];
    float* out = (float*)d_out;
    int n = in_sizes[2];

    cudaFuncSetAttribute(k_fft_zy_fwd,
        cudaFuncAttributeMaxDynamicSharedMemorySize, SMEM_FUSED);
    cudaFuncSetAttribute(k_fft_yz_inv,
        cudaFuncAttributeMaxDynamicSharedMemorySize, SMEM_FUSED);

    k_zero<<<2048, 256>>>();

    int ab = (n + 255) / 256;
    k_scatter<<<ab, 256>>>(cell, pos, chg, n);

    k_fft_zy_fwd<<<128, 1024, SMEM_FUSED>>>();
    k_fft_x_gmul<<<1040, 256>>>(cell);
    k_fft_yz_inv<<<128, 1024, SMEM_FUSED>>>();

    k_gather<<<ab, 256>>>(cell, pos, chg, out, n);
}

// round 17
// speedup vs baseline: 1.0533x; 1.0189x over previous
#include <cuda_runtime.h>
#include <math.h>

#define N3 (128*128*128)
#define NZH 65                       // Hermitian half length along z
#define KLINES (128*65)              // 8320 x-lines; kmesh layout [x][kz][ky]

__device__ float2 d_kmesh[128*KLINES];   // half-spectrum mesh (8.5 MB)
__device__ float  d_rho[N3];             // charge mesh (8 MB) — self-cleaning
__device__ float  d_pot[N3];             // potential mesh (8 MB)

// fused-kernel dynamic smem: plane(65*129) + bufA(32*129) + bufB(32*129) + tw(128)
#define SMEM_FUSED ((65*129 + 32*129 + 32*129 + 128) * 8)

// ---------------------------------------------------------------------------
__device__ __forceinline__ float2 cadd(float2 a, float2 b){ return make_float2(a.x+b.x, a.y+b.y); }
__device__ __forceinline__ float2 csub(float2 a, float2 b){ return make_float2(a.x-b.x, a.y-b.y); }
__device__ __forceinline__ float2 cmul(float2 a, float2 w){ return make_float2(a.x*w.x-a.y*w.y, a.x*w.y+a.y*w.x); }
__device__ __forceinline__ float2 cscale(float2 a, float s){ return make_float2(a.x*s, a.y*s); }

__device__ __forceinline__ void inv3x3(const float* __restrict__ cell,
                                       float inv[9], float& det) {
    float a = __ldg(cell+0), b = __ldg(cell+1), c = __ldg(cell+2);
    float d = __ldg(cell+3), e = __ldg(cell+4), f = __ldg(cell+5);
    float g = __ldg(cell+6), h = __ldg(cell+7), i = __ldg(cell+8);
    float C00 =  (e*i - f*h), C01 = -(d*i - f*g), C02 =  (d*h - e*g);
    float C10 = -(b*i - c*h), C11 =  (a*i - c*g), C12 = -(a*h - b*g);
    float C20 =  (b*f - c*e), C21 = -(a*f - c*d), C22 =  (a*e - b*d);
    det = a*C00 + b*C01 + c*C02;
    float idet = 1.0f / det;
    inv[0]=C00*idet; inv[1]=C10*idet; inv[2]=C20*idet;
    inv[3]=C01*idet; inv[4]=C11*idet; inv[5]=C21*idet;
    inv[6]=C02*idet; inv[7]=C12*idet; inv[8]=C22*idet;
}

// ---------------------------------------------------------------------------
// Radix-4 Stockham stage — per-warp line ownership; lane = butterfly index.
// ---------------------------------------------------------------------------
template<int CONJ, int S>
__device__ __forceinline__ void r4_stage(const float2* __restrict__ cur,
                                         float2* __restrict__ nxt,
                                         const float2* __restrict__ tw,
                                         int off, int t) {
    int q  = t & (S - 1);
    int sp = t - q;
    float2 a0 = cur[off + t];
    float2 a1 = cur[off + t + 32];
    float2 a2 = cur[off + t + 64];
    float2 a3 = cur[off + t + 96];
    float2 t02 = cadd(a0, a2), d02 = csub(a0, a2);
    float2 t13 = cadd(a1, a3), d13 = csub(a1, a3);
    float2 y0 = cadd(t02, t13);
    float2 y2 = csub(t02, t13);
    float2 jd;
    if (CONJ) jd = make_float2(-d13.y,  d13.x);
    else      jd = make_float2( d13.y, -d13.x);
    float2 y1 = cadd(d02, jd);
    float2 y3 = csub(d02, jd);
    float2 w1 = tw[sp], w2 = tw[2*sp], w3 = tw[3*sp];
    if (CONJ) { w1.y = -w1.y; w2.y = -w2.y; w3.y = -w3.y; }
    int o = off + t + 3*sp;
    nxt[o]       = y0;
    nxt[o + S]   = cmul(y1, w1);
    nxt[o + 2*S] = cmul(y2, w2);
    nxt[o + 3*S] = cmul(y3, w3);
}

template<int CONJ>
__device__ __forceinline__ void fft_r4_stages(float2* A, float2* B,
                                              const float2* tw,
                                              int off, int lane) {
    r4_stage<CONJ, 1 >(A, B, tw, off, lane); __syncwarp();
    r4_stage<CONJ, 4 >(B, A, tw, off, lane); __syncwarp();
    r4_stage<CONJ, 16>(A, B, tw, off, lane); __syncwarp();
    // result (pre final radix-2) in B
}

__device__ __forceinline__ void r2_final_warp(const float2* __restrict__ src,
                                              float2* __restrict__ dst,
                                              int off, int lane) {
    #pragma unroll
    for (int t = lane; t < 64; t += 32) {
        float2 a = src[off + t], b = src[off + t + 64];
        dst[off + t]      = cadd(a, b);
        dst[off + t + 64] = csub(a, b);
    }
}

__device__ __forceinline__ void init_tw(float2* tw, int tid) {
    if (tid < 128) {
        float s, c;
        sincospif((float)tid * (1.0f / 64.0f), &s, &c);
        tw[tid] = make_float2(c, -s);
    }
}

// ---------------------------------------------------------------------------
// FUSED forward: per x-plane, z-FFT (r2c two-for-one over y-pairs) into a
// shared plane P[kz][y] (zeroing rho as it reads), then y-FFT per kz,
// contiguous store to kmesh[x][kz][ky]. 128 blocks x 1024 threads.
// ---------------------------------------------------------------------------
__global__ __launch_bounds__(1024, 1) void k_fft_zy_fwd() {
    extern __shared__ float2 sm[];
    float2* P    = sm;                       // 65 * 129
    float2* bufA = sm + 65*129;              // 32 * 129
    float2* bufB = bufA + 32*129;            // 32 * 129
    float2* tw   = bufB + 32*129;            // 128
    int tid = threadIdx.x, lane = tid & 31, w = tid >> 5;
    int off = w * 129;
    int x = blockIdx.x;
    init_tw(tw, tid);
    float* rhoX = d_rho + x * 16384;
    __syncthreads();                         // tw visible
    // stage 1: 64 packed z-FFTs (pairs y=2p, 2p+1), 2 per warp
    for (int p = w; p < 64; p += 32) {
        float* rA = rhoX + (2*p) * 128;
        float* rB = rA + 128;
        #pragma unroll
        for (int l = lane; l < 128; l += 32) {
            bufA[off + l] = make_float2(rA[l], rB[l]);
            rA[l] = 0.0f;                    // self-clean for next replay
            rB[l] = 0.0f;
        }
        __syncwarp();
        fft_r4_stages<0>(bufA, bufB, tw, off, lane);
        r2_final_warp(bufB, bufA, off, lane);
        __syncwarp();
        // Hermitian unpack into P[k][y]
        for (int k = lane; k < 65; k += 32) {
            float2 Ck = bufA[off + k];
            float2 Cm = bufA[off + ((128 - k) & 127)];
            P[k*129 + 2*p]     = make_float2(0.5f*(Ck.x + Cm.x),  0.5f*(Ck.y - Cm.y));
            P[k*129 + 2*p + 1] = make_float2(0.5f*(Ck.y + Cm.y), -0.5f*(Ck.x - Cm.x));
        }
        __syncwarp();
    }
    __syncthreads();
    // stage 2: 65 y-FFTs, contiguous store
    float2* kX = d_kmesh + x * KLINES;
    for (int L = w; L < 65; L += 32) {
        #pragma unroll
        for (int l = lane; l < 128; l += 32)
            bufA[off + l] = P[L*129 + l];
        __syncwarp();
        fft_r4_stages<0>(bufA, bufB, tw, off, lane);
        #pragma unroll
        for (int t = lane; t < 64; t += 32) {
            float2 a = bufB[off + t], b = bufB[off + t + 64];
            kX[L*128 + t]      = cadd(a, b);
            kX[L*128 + t + 64] = csub(a, b);
        }
        __syncwarp();
    }
}

// ---------------------------------------------------------------------------
// FUSED inverse: per x-plane, inverse y-FFT per kz into P[kz][y], then
// inverse z c2r (two-for-one) writing the potential plane. 128 blocks x 1024.
// ---------------------------------------------------------------------------
__global__ __launch_bounds__(1024, 1) void k_fft_yz_inv() {
    extern __shared__ float2 sm[];
    float2* P    = sm;
    float2* bufA = sm + 65*129;
    float2* bufB = bufA + 32*129;
    float2* tw   = bufB + 32*129;
    int tid = threadIdx.x, lane = tid & 31, w = tid >> 5;
    int off = w * 129;
    int x = blockIdx.x;
    init_tw(tw, tid);
    const float2* kX = d_kmesh + x * KLINES;
    __syncthreads();                         // tw visible
    // stage 1: 65 inverse y-FFTs into P[kz][y]
    for (int L = w; L < 65; L += 32) {
        #pragma unroll
        for (int l = lane; l < 128; l += 32)
            bufA[off + l] = kX[L*128 + l];
        __syncwarp();
        fft_r4_stages<1>(bufA, bufB, tw, off, lane);
        #pragma unroll
        for (int t = lane; t < 64; t += 32) {
            float2 a = bufB[off + t], b = bufB[off + t + 64];
            P[L*129 + t]      = cadd(a, b);
            P[L*129 + t + 64] = csub(a, b);
        }
        __syncwarp();
    }
    __syncthreads();
    // stage 2: 64 packed inverse z c2r FFTs (pairs y=2p, 2p+1)
    float* potX = d_pot + x * 16384;
    for (int p = w; p < 64; p += 32) {
        int y0 = 2*p, y1 = 2*p + 1;
        for (int k = lane; k < 65; k += 32) {
            float2 A = P[k*129 + y0], B = P[k*129 + y1];
            bufA[off + k] = make_float2(A.x - B.y, A.y + B.x);
            if (k >= 1 && k <= 63)
                bufA[off + 128 - k] = make_float2(A.x + B.y, B.x - A.y);
        }
        __syncwarp();
        fft_r4_stages<1>(bufA, bufB, tw, off, lane);
        float* rA = potX + y0 * 128;
        float* rB = rA + 128;
        #pragma unroll
        for (int l = lane; l < 64; l += 32) {
            float2 a = bufB[off + l], b = bufB[off + l + 64];
            float2 su = cadd(a, b), df = csub(a, b);
            rA[l]      = su.x;
            rB[l]      = su.y;
            rA[l + 64] = df.x;
            rB[l + 64] = df.y;
        }
        __syncwarp();
    }
}

// ---------------------------------------------------------------------------
// Fused x pass + G(k). The forward final-r2, G multiply, and the FIRST
// inverse r4 stage are fused into one shared sweep: lane t reads the pre-r2
// halves at t, t+32, t+64, t+96 (exactly the S=1 butterfly slots), forms
// X[t], X[t+32], X[t+64], X[t+96], scales by g, and runs the conjugate
// butterfly. Shared sweeps per line: 8 -> 6. 1040 blocks.
// ---------------------------------------------------------------------------
__global__ __launch_bounds__(256, 7) void k_fft_x_gmul(const float* __restrict__ cell) {
    __shared__ float2 bufA[8 * 129];
    __shared__ float2 bufB[8 * 129];
    __shared__ float2 tw[128];
    __shared__ float gc[10];                 // Brec row-major + ivol
    int tid = threadIdx.x, lane = tid & 31, w = tid >> 5;
    int off = w * 129;
    int L0 = blockIdx.x * 8;
    init_tw(tw, tid);
    if (tid == 0) {
        float inv[9]; float det;
        inv3x3(cell, inv, det);
        const float TWO_PI = 6.283185307179586f;
        gc[0] = TWO_PI*inv[0]; gc[1] = TWO_PI*inv[3]; gc[2] = TWO_PI*inv[6];
        gc[3] = TWO_PI*inv[1]; gc[4] = TWO_PI*inv[4]; gc[5] = TWO_PI*inv[7];
        gc[6] = TWO_PI*inv[2]; gc[7] = TWO_PI*inv[5]; gc[8] = TWO_PI*inv[8];
        gc[9] = 1.0f / fabsf(det);
    }
    int L = L0 + w;
    int ky = L & 127, kz = L >> 7;
    float mj = (float)(ky - ((ky >= 64) ? 128 : 0));
    float mk = (float)kz;
    // striped coalesced load
    #pragma unroll
    for (int e = tid; e < 1024; e += 256) {
        int c = e & 7, l = e >> 3;
        bufA[c * 129 + l] = d_kmesh[L0 + c + l * KLINES];
    }
    __syncthreads();                         // tw + gc + tiles visible
    // forward stages -> pre-r2 result in B
    fft_r4_stages<0>(bufA, bufB, tw, off, lane);
    // FUSED: r2-final + G + inverse S=1 butterfly (B -> A)
    {
        float jx = mj * gc[3] + mk * gc[6];
        float jy = mj * gc[4] + mk * gc[7];
        float jz = mj * gc[5] + mk * gc[8];
        float ivol = gc[9];
        int t = lane;
        float2 Ba0 = bufB[off + t];
        float2 Ba1 = bufB[off + t + 32];
        float2 Bb0 = bufB[off + t + 64];
        float2 Bb1 = bufB[off + t + 96];
        // X at k = t, t+32, t+64, t+96 (mi = t, t+32, t-64, t-32)
        float2 X0 = cadd(Ba0, Bb0);
        float2 X1 = cadd(Ba1, Bb1);
        float2 X2 = csub(Ba0, Bb0);
        float2 X3 = csub(Ba1, Bb1);
        float mi0 = (float)t;
        float mi1 = (float)(t + 32);
        float mi2 = (float)(t - 64);
        float mi3 = (float)(t - 32);
        float g0, g1, g2, g3;
        {
            float kx, kyv, kzv, ksq;
            kx = mi0*gc[0]+jx; kyv = mi0*gc[1]+jy; kzv = mi0*gc[2]+jz;
            ksq = kx*kx + kyv*kyv + kzv*kzv;
            g0 = (ksq != 0.0f) ? 12.566370614359172f / ksq * expf(-0.5f*ksq) * ivol : 0.0f;
            kx = mi1*gc[0]+jx; kyv = mi1*gc[1]+jy; kzv = mi1*gc[2]+jz;
            ksq = kx*kx + kyv*kyv + kzv*kzv;
            g1 = (ksq != 0.0f) ? 12.566370614359172f / ksq * expf(-0.5f*ksq) * ivol : 0.0f;
            kx = mi2*gc[0]+jx; kyv = mi2*gc[1]+jy; kzv = mi2*gc[2]+jz;
            ksq = kx*kx + kyv*kyv + kzv*kzv;
            g2 = (ksq != 0.0f) ? 12.566370614359172f / ksq * expf(-0.5f*ksq) * ivol : 0.0f;
            kx = mi3*gc[0]+jx; kyv = mi3*gc[1]+jy; kzv = mi3*gc[2]+jz;
            ksq = kx*kx + kyv*kyv + kzv*kzv;
            g3 = (ksq != 0.0f) ? 12.566370614359172f / ksq * expf(-0.5f*ksq) * ivol : 0.0f;
        }
        float2 a0 = cscale(X0, g0);
        float2 a1 = cscale(X1, g1);
        float2 a2 = cscale(X2, g2);
        float2 a3 = cscale(X3, g3);
        // conjugate (inverse) radix-4 S=1 butterfly
        float2 t02 = cadd(a0, a2), d02 = csub(a0, a2);
        float2 t13 = cadd(a1, a3), d13 = csub(a1, a3);
        float2 y0 = cadd(t02, t13);
        float2 y2 = csub(t02, t13);
        float2 jd = make_float2(-d13.y, d13.x);     // CONJ
        float2 y1 = cadd(d02, jd);
        float2 y3 = csub(d02, jd);
        float2 w1 = tw[t], w2 = tw[2*t], w3 = tw[(3*t) & 127];
        w1.y = -w1.y; w2.y = -w2.y; w3.y = -w3.y;   // conj
        int o = off + 4*t;
        bufA[o]     = y0;
        bufA[o + 1] = cmul(y1, w1);
        bufA[o + 2] = cmul(y2, w2);
        bufA[o + 3] = cmul(y3, w3);
    }
    __syncwarp();
    // remaining inverse stages: S=4 (A->B), S=16 (B->A)
    r4_stage<1, 4 >(bufA, bufB, tw, off, lane); __syncwarp();
    r4_stage<1, 16>(bufB, bufA, tw, off, lane);
    __syncthreads();
    // striped coalesced store with fused final radix-2 (reads bufA)
    #pragma unroll
    for (int e = tid; e < 512; e += 256) {
        int c = e & 7, l = e >> 3;
        float2 a = bufA[c * 129 + l], b = bufA[c * 129 + l + 64];
        d_kmesh[L0 + c + l * KLINES]        = cadd(a, b);
        d_kmesh[L0 + c + (l + 64) * KLINES] = csub(a, b);
    }
}

// ---------------------------------------------------------------------------
// spline weights + stencil
// ---------------------------------------------------------------------------
__device__ __forceinline__ void spline_w4(float x, float* w) {
    float x2 = x * x, x3 = x2 * x;
    const float s = 1.0f / 48.0f;
    w[0] = ( 1.0f -  6.0f*x + 12.0f*x2 -  8.0f*x3) * s;
    w[1] = (23.0f - 30.0f*x - 12.0f*x2 + 24.0f*x3) * s;
    w[2] = (23.0f + 30.0f*x - 12.0f*x2 - 24.0f*x3) * s;
    w[3] = ( 1.0f +  6.0f*x + 12.0f*x2 +  8.0f*x3) * s;
}

__device__ __forceinline__ int atom_stencil(
    const float* __restrict__ cell, const float* __restrict__ pos, int a,
    float* wx, float* wy, float* wz, int* ix, int* iy)
{
    float inv[9]; float det;
    inv3x3(cell, inv, det);
    float p0 = pos[3*a], p1 = pos[3*a+1], p2 = pos[3*a+2];
    float r0 = (p0*inv[0] + p1*inv[3] + p2*inv[6]) * 128.0f;
    float r1 = (p0*inv[1] + p1*inv[4] + p2*inv[7]) * 128.0f;
    float r2 = (p0*inv[2] + p1*inv[5] + p2*inv[8]) * 128.0f;
    int i0 = __float2int_rd(r0);
    int i1 = __float2int_rd(r1);
    int i2 = __float2int_rd(r2);
    spline_w4(r0 - (float)i0 - 0.5f, wx);
    spline_w4(r1 - (float)i1 - 0.5f, wy);
    spline_w4(r2 - (float)i2 - 0.5f, wz);
    #pragma unroll
    for (int s = 0; s < 4; s++) {
        ix[s] = (i0 + s - 1 + 128) & 127;
        iy[s] = (i1 + s - 1 + 128) & 127;
    }
    return i2;
}

__device__ __forceinline__ void pad_quads(const float* wz, int off,
                                          float* q0, float* q1) {
    switch (off) {
    case 0: q0[0]=wz[0]; q0[1]=wz[1]; q0[2]=wz[2]; q0[3]=wz[3]; break;
    case 1: q0[1]=wz[0]; q0[2]=wz[1]; q0[3]=wz[2]; q1[0]=wz[3]; break;
    case 2: q0[2]=wz[0]; q0[3]=wz[1]; q1[0]=wz[2]; q1[1]=wz[3]; break;
    default:q0[3]=wz[0]; q1[0]=wz[1]; q1[1]=wz[2]; q1[2]=wz[3]; break;
    }
}

__device__ __forceinline__ void red4(float* p, float a, float b, float c, float d) {
    asm volatile("red.global.add.v4.f32 [%0], {%1, %2, %3, %4};"
                 :: "l"(p), "f"(a), "f"(b), "f"(c), "f"(d) : "memory");
}
__device__ __forceinline__ void red2(float* p, float a, float b) {
    asm volatile("red.global.add.v2.f32 [%0], {%1, %2};"
                 :: "l"(p), "f"(a), "f"(b) : "memory");
}
__device__ __forceinline__ void red1(float* p, float a) {
    asm volatile("red.global.add.f32 [%0], %1;"
                 :: "l"(p), "f"(a) : "memory");
}

// ---------------------------------------------------------------------------
__global__ void k_scatter(const float* __restrict__ cell,
                          const float* __restrict__ pos,
                          const float* __restrict__ chg, int n) {
    int a = blockIdx.x * blockDim.x + threadIdx.x;
    if (a >= n) return;
    float wx[4], wy[4], wz[4];
    int ix[4], iy[4];
    int i2 = atom_stencil(cell, pos, a, wx, wy, wz, ix, iy);
    float c = chg[a];
    int zlo = i2 - 1;
    if (zlo >= 0 && zlo <= 124) {
        int Q0 = zlo & ~3, off = zlo & 3;
        #pragma unroll
        for (int i = 0; i < 4; i++) {
            float cwi = c * wx[i];
            int ox = ix[i] << 14;
            #pragma unroll
            for (int j = 0; j < 4; j++) {
                float s = cwi * wy[j];
                float* p = &d_rho[ox + (iy[j] << 7) + Q0];
                switch (off) {
                case 0:
                    red4(p, s*wz[0], s*wz[1], s*wz[2], s*wz[3]);
                    break;
                case 1:
                    red4(p, 0.0f, s*wz[0], s*wz[1], s*wz[2]);
                    red1(p + 4, s*wz[3]);
                    break;
                case 2:
                    red2(p + 2, s*wz[0], s*wz[1]);
                    red2(p + 4, s*wz[2], s*wz[3]);
                    break;
                default:
                    red1(p + 3, s*wz[0]);
                    red4(p + 4, s*wz[1], s*wz[2], s*wz[3], 0.0f);
                    break;
                }
            }
        }
    } else {
        int iz[4];
        #pragma unroll
        for (int s = 0; s < 4; s++) iz[s] = (zlo + s + 128) & 127;
        #pragma unroll
        for (int i = 0; i < 4; i++) {
            float cwi = c * wx[i];
            int ox = ix[i] << 14;
            #pragma unroll
            for (int j = 0; j < 4; j++) {
                float cwij = cwi * wy[j];
                int oxy = ox + (iy[j] << 7);
                #pragma unroll
                for (int k = 0; k < 4; k++)
                    red1(&d_rho[oxy + iz[k]], cwij * wz[k]);
            }
        }
    }
}

// ---------------------------------------------------------------------------
__global__ void k_gather(const float* __restrict__ cell,
                         const float* __restrict__ pos,
                         const float* __restrict__ chg,
                         float* __restrict__ out, int n) {
    int a = blockIdx.x * blockDim.x + threadIdx.x;
    if (a >= n) return;
    float wx[4], wy[4], wz[4];
    int ix[4], iy[4];
    int i2 = atom_stencil(cell, pos, a, wx, wy, wz, ix, iy);
    float sum = 0.0f;
    int zlo = i2 - 1;
    if (zlo >= 0 && zlo <= 124) {
        int Q0 = zlo & ~3, off = zlo & 3;
        float q0[4] = {0,0,0,0}, q1[4] = {0,0,0,0};
        pad_quads(wz, off, q0, q1);
        #pragma unroll
        for (int i = 0; i < 4; i++) {
            float wi = wx[i];
            int ox = ix[i] << 14;
            #pragma unroll
            for (int j = 0; j < 4; j++) {
                const float* p = &d_pot[ox + (iy[j] << 7) + Q0];
                float4 v0 = __ldg((const float4*)p);
                float acc = v0.x*q0[0] + v0.y*q0[1] + v0.z*q0[2] + v0.w*q0[3];
                if (off) {
                    float4 v1 = __ldg((const float4*)(p + 4));
                    acc += v1.x*q1[0] + v1.y*q1[1] + v1.z*q1[2] + v1.w*q1[3];
                }
                sum += wi * wy[j] * acc;
            }
        }
    } else {
        int iz[4];
        #pragma unroll
        for (int s = 0; s < 4; s++) iz[s] = (zlo + s + 128) & 127;
        #pragma unroll
        for (int i = 0; i < 4; i++) {
            float wi = wx[i];
            int ox = ix[i] << 14;
            #pragma unroll
            for (int j = 0; j < 4; j++) {
                int oxy = ox + (iy[j] << 7);
                float acc = 0.0f;
                #pragma unroll
                for (int k = 0; k < 4; k++)
                    acc += wz[k] * d_pot[oxy + iz[k]];
                sum += wi * wy[j] * acc;
            }
        }
    }
    out[a] = sum - chg[a] * 0.7978845608028654f;
}

// ---------------------------------------------------------------------------
extern "C" void kernel_launch(void* const* d_in, const int* in_sizes, int n_in,
                              void* d_out, int out_size) {
    const float* cell = (const float*)d_in[0];
    const float* pos  = (const float*)d_in[1];
    const float* chg  = (const float*)d_in[2];
    float* out = (float*)d_out;
    int n = in_sizes[2];

    cudaFuncSetAttribute(k_fft_zy_fwd,
        cudaFuncAttributeMaxDynamicSharedMemorySize, SMEM_FUSED);
    cudaFuncSetAttribute(k_fft_yz_inv,
        cudaFuncAttributeMaxDynamicSharedMemorySize, SMEM_FUSED);

    int ab = (n + 255) / 256;
    k_scatter<<<ab, 256>>>(cell, pos, chg, n);

    k_fft_zy_fwd<<<128, 1024, SMEM_FUSED>>>();
    k_fft_x_gmul<<<1040, 256>>>(cell);
    k_fft_yz_inv<<<128, 1024, SMEM_FUSED>>>();

    k_gather<<<ab, 256>>>(cell, pos, chg, out, n);
}